// round 7
// baseline (speedup 1.0000x reference)
#include <cuda_runtime.h>
#include <cuda_bf16.h>
#include <cstdint>

// Shapes
#define M_TOTAL 10752          // B*T*N = 8*64*21
#define C_IN    128
#define F_OUT   256
#define N_SP    21
#define BM      64
#define MT      (M_TOTAL / BM) // 168 m-tiles

// SMEM (bytes). bf16 tiles padded to 136 elems/row (272B) for conflict-free ldmatrix.
#define TSTR    272
#define SM_AHI  0
#define SM_ALO  (SM_AHI + 64  * TSTR)     // 17408
#define SM_BHI  (SM_ALO + 64  * TSTR)     // 34816
#define SM_BLO  (SM_BHI + 128 * TSTR)     // 69632
#define SM_PS   (SM_BLO + 128 * TSTR)     // 104448
#define SM_PQ   (SM_PS + 1024)
#define SM_TOT  (SM_PQ + 1024)            // 106496 -> 2 CTAs/SM
#define YS      132                        // y staging stride (floats)

// Scratch (allocation-free device globals)
__device__ float g_psum[MT * F_OUT];
__device__ float g_psq [MT * F_OUT];
__device__ float g_scale[F_OUT];
__device__ float g_shift[F_OUT];
__device__ __nv_bfloat162 g_Bh[F_OUT * 64];   // B hi: [f][k] row-major, k-pairs
__device__ __nv_bfloat162 g_Bl[F_OUT * 64];   // B lo

__device__ __forceinline__ uint32_t smem_u32(const void* p) {
    uint32_t a;
    asm("{ .reg .u64 t; cvta.to.shared.u64 t, %1; cvt.u32.u64 %0, t; }"
        : "=r"(a) : "l"(p));
    return a;
}
__device__ __forceinline__ void ldsm4(uint32_t* r, uint32_t addr) {
    asm volatile("ldmatrix.sync.aligned.m8n8.x4.shared.b16 {%0,%1,%2,%3}, [%4];"
        : "=r"(r[0]), "=r"(r[1]), "=r"(r[2]), "=r"(r[3]) : "r"(addr));
}
__device__ __forceinline__ void mma16816(float* d, const uint32_t* a,
                                         uint32_t b0, uint32_t b1) {
    asm volatile("mma.sync.aligned.m16n8k16.row.col.f32.bf16.bf16.f32 "
        "{%0,%1,%2,%3}, {%4,%5,%6,%7}, {%8,%9}, {%0,%1,%2,%3};"
        : "+f"(d[0]), "+f"(d[1]), "+f"(d[2]), "+f"(d[3])
        : "r"(a[0]), "r"(a[1]), "r"(a[2]), "r"(a[3]), "r"(b0), "r"(b1));
}
__device__ __forceinline__ __nv_bfloat162 split_pair(float v0, float v1, float2& res) {
    __nv_bfloat162 h;
    h.x = __float2bfloat16(v0); h.y = __float2bfloat16(v1);
    res.x = v0 - __bfloat162float(h.x);
    res.y = v1 - __bfloat162float(h.y);
    return h;
}

// ---- shared mainloop: gather/split A, copy B, 3-product bf16 MMA ----
// acc[8][4]: atom (p*2+u), p in 0..3 (n16 pairs), u in 0..1 (n8 within pair)
__device__ __forceinline__ void gemm_mainloop(const float* __restrict__ x,
                                              char* smem, uint32_t sb,
                                              int tid, int ftile, int m0,
                                              float acc[8][4]) {
    // B tiles: copy pre-split bf16 [128f][128k] into padded smem
    {
        const float4* srcH = (const float4*)(g_Bh + ftile * 128 * 64);
        const float4* srcL = (const float4*)(g_Bl + ftile * 128 * 64);
        #pragma unroll
        for (int i = 0; i < 8; ++i) {
            int chunk = i * 256 + tid;          // 2048 chunks of 16B
            int r = chunk >> 4, c = chunk & 15;
            *(float4*)(smem + SM_BHI + r * TSTR + c * 16) = srcH[chunk];
            *(float4*)(smem + SM_BLO + r * TSTR + c * 16) = srcL[chunk];
        }
    }
    // A tile: shift-gather + hi/lo split. Thread -> (row, k-quarter).
    {
        const int row = tid >> 2;               // 0..63
        const int q   = tid & 3;                // 32 k each
        const int r  = m0 + row;
        const int bt = r / N_SP;
        const int n  = r - bt * N_SP;
        const int bt21 = bt * N_SP;
        const int c0 = q * 32;
        int s = c0 % N_SP;
        char* dh = smem + SM_AHI + row * TSTR + c0 * 2;
        char* dl = smem + SM_ALO + row * TSTR + c0 * 2;
        #pragma unroll 8
        for (int j = 0; j < 16; ++j) {
            const int c = c0 + 2 * j;
            int s1 = s + 1; if (s1 >= N_SP) s1 -= N_SP;
            int n0 = n - s;  n0 += (n0 >> 31) & N_SP;
            int n1 = n - s1; n1 += (n1 >> 31) & N_SP;
            float v0 = x[(bt21 + n0) * C_IN + c];
            float v1 = x[(bt21 + n1) * C_IN + c + 1];
            float2 lo;
            __nv_bfloat162 hi = split_pair(v0, v1, lo);
            __nv_bfloat162 lp;
            lp.x = __float2bfloat16(lo.x); lp.y = __float2bfloat16(lo.y);
            *(__nv_bfloat162*)(dh + 4 * j) = hi;
            *(__nv_bfloat162*)(dl + 4 * j) = lp;
            s += 2; if (s >= N_SP) s -= N_SP;
        }
    }
    __syncthreads();

    const int lane = tid & 31, wid = tid >> 5;
    const int warp_m = wid & 3, warp_f = wid >> 2;
    const int j = lane & 7, g = lane >> 3;

    // ldmatrix lane addresses
    const uint32_t aoff = (uint32_t)((warp_m * 16 + j + ((g & 1) << 3)) * TSTR
                                     + ((g >> 1) * 8) * 2);
    const uint32_t boff = (uint32_t)((warp_f * 64 + j + ((g >> 1) << 3)) * TSTR
                                     + ((g & 1) * 8) * 2);
    const uint32_t aHI = sb + SM_AHI + aoff, aLO = sb + SM_ALO + aoff;
    const uint32_t bHI = sb + SM_BHI + boff, bLO = sb + SM_BLO + boff;

    #pragma unroll
    for (int ks = 0; ks < 8; ++ks) {
        const uint32_t kb = ks * 32;            // 16 k * 2B
        uint32_t ah[4], al[4];
        ldsm4(ah, aHI + kb);
        ldsm4(al, aLO + kb);
        #pragma unroll
        for (int p = 0; p < 4; ++p) {
            const uint32_t pb = p * 16 * TSTR + kb;
            uint32_t bh[4], bl[4];
            ldsm4(bh, bHI + pb);
            ldsm4(bl, bLO + pb);
            mma16816(acc[p * 2],     ah, bh[0], bh[1]);   // hh
            mma16816(acc[p * 2 + 1], ah, bh[2], bh[3]);
            mma16816(acc[p * 2],     ah, bl[0], bl[1]);   // hl
            mma16816(acc[p * 2 + 1], ah, bl[2], bl[3]);
            mma16816(acc[p * 2],     al, bh[0], bh[1]);   // lh
            mma16816(acc[p * 2 + 1], al, bh[2], bh[3]);
        }
    }
}

// K0: split W into bf16 hi/lo, stored [f][k] row-major for ldmatrix-B
__global__ __launch_bounds__(256) void wsplit_kernel(const float* __restrict__ W) {
    const int idx = blockIdx.x * 256 + threadIdx.x;   // 64 blocks -> 16384
    const int f = idx >> 6;
    const int jj = idx & 63;
    const int c = 2 * jj;
    float v0 = W[c * F_OUT + f];
    float v1 = W[(c + 1) * F_OUT + f];
    float2 lo;
    __nv_bfloat162 hi = split_pair(v0, v1, lo);
    __nv_bfloat162 lp;
    lp.x = __float2bfloat16(lo.x); lp.y = __float2bfloat16(lo.y);
    g_Bh[f * 64 + jj] = hi;
    g_Bl[f * 64 + jj] = lp;
}

// K1: GEMM -> BN partial sums only (y never touches DRAM)
__global__ __launch_bounds__(256, 2) void gemm1_kernel(const float* __restrict__ x) {
    extern __shared__ char smem[];
    const uint32_t sb = smem_u32(smem);
    const int tid = threadIdx.x;
    const int ftile = blockIdx.x;            // 0..1
    const int mtile = blockIdx.y;            // 0..167

    float acc[8][4];
    #pragma unroll
    for (int a = 0; a < 8; ++a)
        #pragma unroll
        for (int e = 0; e < 4; ++e) acc[a][e] = 0.f;

    gemm_mainloop(x, smem, sb, tid, ftile, mtile * BM, acc);
    __syncthreads();                          // A region dead -> reuse as Y

    // stage y tile [64][YS] in smem (overlaps A hi/lo region: 33792B <= 34816B)
    float* Y  = (float*)(smem + SM_AHI);
    float* Ps = (float*)(smem + SM_PS);
    float* Pq = (float*)(smem + SM_PQ);
    {
        const int lane = tid & 31, wid = tid >> 5;
        const int warp_m = wid & 3, warp_f = wid >> 2;
        const int r0 = warp_m * 16 + (lane >> 2);
        #pragma unroll
        for (int p = 0; p < 4; ++p)
            #pragma unroll
            for (int u = 0; u < 2; ++u) {
                const int col = warp_f * 64 + p * 16 + u * 8 + (lane & 3) * 2;
                float* d = acc[p * 2 + u];
                *(float2*)&Y[r0 * YS + col]       = make_float2(d[0], d[1]);
                *(float2*)&Y[(r0 + 8) * YS + col] = make_float2(d[2], d[3]);
            }
    }
    __syncthreads();
    {
        const int part = tid >> 7, f = tid & 127;   // 2 parts x 32 rows
        float s = 0.f, q = 0.f;
        #pragma unroll 8
        for (int r = 0; r < 32; ++r) {
            float v = Y[(part * 32 + r) * YS + f];
            s += v; q += v * v;
        }
        Ps[part * 128 + f] = s;
        Pq[part * 128 + f] = q;
    }
    __syncthreads();
    if (tid < 128) {
        g_psum[mtile * F_OUT + ftile * 128 + tid] = Ps[tid] + Ps[128 + tid];
        g_psq [mtile * F_OUT + ftile * 128 + tid] = Pq[tid] + Pq[128 + tid];
    }
}

// K2: finalize BN stats -> scale/shift (conv bias cancels exactly in BN)
__global__ __launch_bounds__(1024) void stats_kernel(const float* __restrict__ gamma,
                                                     const float* __restrict__ beta) {
    __shared__ float ss[4][256], sq[4][256];
    const int tid = threadIdx.x;
    const int f = tid & 255;
    const int g = tid >> 8;              // 0..3, 42 tiles each
    float s = 0.f, q = 0.f;
    #pragma unroll 6
    for (int t = g * 42; t < (g + 1) * 42; ++t) {
        s += g_psum[t * F_OUT + f];
        q += g_psq [t * F_OUT + f];
    }
    ss[g][f] = s; sq[g][f] = q;
    __syncthreads();
    if (g == 0) {
        s = ss[0][f] + ss[1][f] + ss[2][f] + ss[3][f];
        q = sq[0][f] + sq[1][f] + sq[2][f] + sq[3][f];
        const float inv = 1.0f / (float)M_TOTAL;
        float mean = s * inv;
        float var  = q * inv - mean * mean;
        float sc   = gamma[f] * rsqrtf(var + 1e-3f);
        g_scale[f] = sc;
        g_shift[f] = beta[f] - mean * sc;
    }
}

// K3: bit-identical GEMM, normalize + relu straight from accumulators
__global__ __launch_bounds__(256, 2) void gemm2_kernel(const float* __restrict__ x,
                                                       float* __restrict__ out) {
    extern __shared__ char smem[];
    const uint32_t sb = smem_u32(smem);
    const int tid = threadIdx.x;
    const int ftile = blockIdx.x;
    const int mtile = blockIdx.y;
    const int m0 = mtile * BM;

    float acc[8][4];
    #pragma unroll
    for (int a = 0; a < 8; ++a)
        #pragma unroll
        for (int e = 0; e < 4; ++e) acc[a][e] = 0.f;

    gemm_mainloop(x, smem, sb, tid, ftile, m0, acc);

    const int lane = tid & 31, wid = tid >> 5;
    const int warp_m = wid & 3, warp_f = wid >> 2;
    const int r0 = m0 + warp_m * 16 + (lane >> 2);
    #pragma unroll
    for (int p = 0; p < 4; ++p)
        #pragma unroll
        for (int u = 0; u < 2; ++u) {
            const int col = ftile * 128 + warp_f * 64 + p * 16 + u * 8 + (lane & 3) * 2;
            float2 sc = *(const float2*)&g_scale[col];
            float2 sh = *(const float2*)&g_shift[col];
            float* d = acc[p * 2 + u];
            float2 o0, o1;
            o0.x = fmaxf(fmaf(d[0], sc.x, sh.x), 0.f);
            o0.y = fmaxf(fmaf(d[1], sc.y, sh.y), 0.f);
            o1.x = fmaxf(fmaf(d[2], sc.x, sh.x), 0.f);
            o1.y = fmaxf(fmaf(d[3], sc.y, sh.y), 0.f);
            *(float2*)&out[(size_t)r0 * F_OUT + col]       = o0;
            *(float2*)&out[(size_t)(r0 + 8) * F_OUT + col] = o1;
        }
}

extern "C" void kernel_launch(void* const* d_in, const int* in_sizes, int n_in,
                              void* d_out, int out_size) {
    const float* x     = (const float*)d_in[0];
    const float* W     = (const float*)d_in[1];
    // d_in[2] = conv bias b: cancels exactly under BatchNorm -> unused
    const float* gamma = (const float*)d_in[3];
    const float* beta  = (const float*)d_in[4];

    cudaFuncSetAttribute(gemm1_kernel, cudaFuncAttributeMaxDynamicSharedMemorySize, SM_TOT);
    cudaFuncSetAttribute(gemm2_kernel, cudaFuncAttributeMaxDynamicSharedMemorySize, SM_TOT);

    wsplit_kernel<<<64, 256>>>(W);
    gemm1_kernel<<<dim3(2, MT), 256, SM_TOT>>>(x);
    stats_kernel<<<1, 1024>>>(gamma, beta);
    gemm2_kernel<<<dim3(2, MT), 256, SM_TOT>>>(x, (float*)d_out);
}

// round 8
// speedup vs baseline: 2.3213x; 2.3213x over previous
#include <cuda_runtime.h>
#include <cuda_bf16.h>
#include <cstdint>

// Shapes
#define M_TOTAL 10752          // B*T*N = 8*64*21
#define C_IN    128
#define F_OUT   256
#define N_SP    21
#define BM      64
#define MT      (M_TOTAL / BM) // 168 m-tiles

// SMEM: A hi/lo only (bf16, padded rows for conflict-free ldmatrix)
#define TSTR    272
#define SM_AHI  0
#define SM_ALO  (SM_AHI + 64 * TSTR)      // 17408
#define SM_PS   (SM_ALO + 64 * TSTR)      // 34816 (Y staging reuses A region)
#define SM_PQ   (SM_PS + 1024)
#define SM_TOT  (SM_PQ + 1024)            // 36864 -> 3 CTAs/SM
#define YS      132                        // y staging stride (floats)

// Scratch (allocation-free device globals)
__device__ float g_y[M_TOTAL * F_OUT];       // 11 MB pre-BN activations
__device__ float g_psum[MT * F_OUT];
__device__ float g_psq [MT * F_OUT];
__device__ float g_scale[F_OUT];
__device__ float g_shift[F_OUT];
// W as per-lane mma B-fragments: [ft][wf][hl][ks][p][lane] -> uint4 {u0b0,u0b1,u1b0,u1b1}
__device__ uint4 g_Bfrag[8192];              // 128 KB, L1-resident

__device__ __forceinline__ uint32_t smem_u32(const void* p) {
    uint32_t a;
    asm("{ .reg .u64 t; cvta.to.shared.u64 t, %1; cvt.u32.u64 %0, t; }"
        : "=r"(a) : "l"(p));
    return a;
}
__device__ __forceinline__ void ldsm4(uint32_t* r, uint32_t addr) {
    asm volatile("ldmatrix.sync.aligned.m8n8.x4.shared.b16 {%0,%1,%2,%3}, [%4];"
        : "=r"(r[0]), "=r"(r[1]), "=r"(r[2]), "=r"(r[3]) : "r"(addr));
}
__device__ __forceinline__ void mma16816(float* d, const uint32_t* a,
                                         uint32_t b0, uint32_t b1) {
    asm volatile("mma.sync.aligned.m16n8k16.row.col.f32.bf16.bf16.f32 "
        "{%0,%1,%2,%3}, {%4,%5,%6,%7}, {%8,%9}, {%0,%1,%2,%3};"
        : "+f"(d[0]), "+f"(d[1]), "+f"(d[2]), "+f"(d[3])
        : "r"(a[0]), "r"(a[1]), "r"(a[2]), "r"(a[3]), "r"(b0), "r"(b1));
}

// K0: split W into bf16 hi/lo, stored directly as mma B-fragments per lane
__global__ __launch_bounds__(256) void wsplit_kernel(const float* __restrict__ W) {
    const int idx  = blockIdx.x * 256 + threadIdx.x;  // 0..8191
    const int lane = idx & 31;
    const int p    = (idx >> 5) & 3;
    const int ks   = (idx >> 7) & 7;
    const int hl   = (idx >> 10) & 1;
    const int wf   = (idx >> 11) & 1;
    const int ft   = (idx >> 12) & 1;
    const int F0 = ft * 128 + wf * 64 + p * 16 + (lane >> 2);
    const int k0 = ks * 16 + (lane & 3) * 2;

    auto elem = [&](int k, int f) -> __nv_bfloat16 {
        float v = W[k * F_OUT + f];
        __nv_bfloat16 h = __float2bfloat16(v);
        if (!hl) return h;
        return __float2bfloat16(v - __bfloat162float(h));
    };
    auto pk = [&](int k, int f) -> uint32_t {
        __nv_bfloat162 t; t.x = elem(k, f); t.y = elem(k + 1, f);
        return *(uint32_t*)&t;
    };
    uint4 r;
    r.x = pk(k0,     F0);
    r.y = pk(k0 + 8, F0);
    r.z = pk(k0,     F0 + 8);
    r.w = pk(k0 + 8, F0 + 8);
    g_Bfrag[idx] = r;
}

// K1: fused shift+GEMM (bf16x3 HMMA) -> y + BN partials
// grid (2, 168), 256 threads, 3 CTAs/SM.
__global__ __launch_bounds__(256, 3) void gemm_kernel(const float* __restrict__ x) {
    extern __shared__ char smem[];
    const uint32_t sb = smem_u32(smem);
    const int tid   = threadIdx.x;
    const int ftile = blockIdx.x;            // 0..1
    const int mtile = blockIdx.y;            // 0..167
    const int m0    = mtile * BM;

    // ---- A: coalesced float4 load of 4 whole bt-groups, shift applied on store ----
    {
        const int gs = m0 / N_SP;            // tile always spans groups gs..gs+3
        const float* xb = x + gs * N_SP * C_IN;
        #pragma unroll
        for (int it = 0; it < 11; ++it) {
            const int idx = it * 256 + tid;  // 84 rows * 32 float4 = 2688
            if (idx < 2688) {
                const int rl = idx >> 5;
                const int c4 = (idx & 31) * 4;
                float4 v = *(const float4*)&xb[rl * C_IN + c4];
                const int g   = rl / N_SP;
                const int inn = rl - g * N_SP;
                const int bm  = (gs + g) * N_SP - m0;
                const float vv[4] = { v.x, v.y, v.z, v.w };
                #pragma unroll
                for (int e = 0; e < 4; ++e) {
                    const int c = c4 + e;
                    int on = inn + c % N_SP;
                    if (on >= N_SP) on -= N_SP;
                    const int lm = bm + on;
                    if (lm >= 0 && lm < 64) {
                        float val = vv[e];
                        __nv_bfloat16 h = __float2bfloat16(val);
                        __nv_bfloat16 l = __float2bfloat16(val - __bfloat162float(h));
                        *(__nv_bfloat16*)(smem + SM_AHI + lm * TSTR + c * 2) = h;
                        *(__nv_bfloat16*)(smem + SM_ALO + lm * TSTR + c * 2) = l;
                    }
                }
            }
        }
    }
    __syncthreads();

    // ---- mainloop: A via ldmatrix, B via direct global fragment loads ----
    const int lane = tid & 31, wid = tid >> 5;
    const int warp_m = wid & 3, warp_f = wid >> 2;
    const int j = lane & 7, g = lane >> 3;
    const uint32_t aoff = (uint32_t)((warp_m * 16 + j + ((g & 1) << 3)) * TSTR
                                     + ((g >> 1) * 8) * 2);
    const uint32_t aHI = sb + SM_AHI + aoff, aLO = sb + SM_ALO + aoff;
    const uint4* BH = g_Bfrag + (ftile * 2 + warp_f) * 2048 + lane;
    const uint4* BL = BH + 1024;

    float acc[8][4];
    #pragma unroll
    for (int a = 0; a < 8; ++a)
        #pragma unroll
        for (int e = 0; e < 4; ++e) acc[a][e] = 0.f;

    #pragma unroll
    for (int ks = 0; ks < 8; ++ks) {
        uint32_t ah[4], al[4];
        ldsm4(ah, aHI + ks * 32);
        ldsm4(al, aLO + ks * 32);
        #pragma unroll
        for (int p = 0; p < 4; ++p) {
            const uint4 bh = __ldg(BH + (ks * 4 + p) * 32);
            const uint4 bl = __ldg(BL + (ks * 4 + p) * 32);
            mma16816(acc[p * 2],     ah, bh.x, bh.y);   // hh
            mma16816(acc[p * 2 + 1], ah, bh.z, bh.w);
            mma16816(acc[p * 2],     ah, bl.x, bl.y);   // hl
            mma16816(acc[p * 2 + 1], ah, bl.z, bl.w);
            mma16816(acc[p * 2],     al, bh.x, bh.y);   // lh
            mma16816(acc[p * 2 + 1], al, bh.z, bh.w);
        }
    }
    __syncthreads();                          // A region dead -> reuse as Y

    // ---- epilogue: stage y, BN partials, coalesced y store ----
    float* Y  = (float*)(smem + SM_AHI);      // [64][YS]
    float* Ps = (float*)(smem + SM_PS);
    float* Pq = (float*)(smem + SM_PQ);
    {
        const int r0 = warp_m * 16 + (lane >> 2);
        #pragma unroll
        for (int p = 0; p < 4; ++p)
            #pragma unroll
            for (int u = 0; u < 2; ++u) {
                const int col = warp_f * 64 + p * 16 + u * 8 + (lane & 3) * 2;
                float* d = acc[p * 2 + u];
                *(float2*)&Y[r0 * YS + col]       = make_float2(d[0], d[1]);
                *(float2*)&Y[(r0 + 8) * YS + col] = make_float2(d[2], d[3]);
            }
    }
    __syncthreads();
    {
        const int part = tid >> 7, f = tid & 127;   // 2 parts x 32 rows
        float s = 0.f, q = 0.f;
        #pragma unroll 8
        for (int r = 0; r < 32; ++r) {
            float v = Y[(part * 32 + r) * YS + f];
            s += v; q += v * v;
        }
        Ps[part * 128 + f] = s;
        Pq[part * 128 + f] = q;
    }
    // y store (coalesced float4): 64 rows x 32 chunks
    #pragma unroll
    for (int i = 0; i < 8; ++i) {
        const int id = i * 256 + tid;
        const int r = id >> 5, c4 = (id & 31) * 4;
        float4 v = *(const float4*)&Y[r * YS + c4];
        *(float4*)&g_y[(size_t)(m0 + r) * F_OUT + ftile * 128 + c4] = v;
    }
    __syncthreads();
    if (tid < 128) {
        g_psum[mtile * F_OUT + ftile * 128 + tid] = Ps[tid] + Ps[128 + tid];
        g_psq [mtile * F_OUT + ftile * 128 + tid] = Pq[tid] + Pq[128 + tid];
    }
}

// K2: finalize BN stats -> scale/shift (conv bias cancels exactly in BN)
__global__ __launch_bounds__(1024) void stats_kernel(const float* __restrict__ gamma,
                                                     const float* __restrict__ beta) {
    __shared__ float ss[4][256], sq[4][256];
    const int tid = threadIdx.x;
    const int f = tid & 255;
    const int g = tid >> 8;              // 0..3, 42 tiles each
    float s = 0.f, q = 0.f;
    #pragma unroll 6
    for (int t = g * 42; t < (g + 1) * 42; ++t) {
        s += g_psum[t * F_OUT + f];
        q += g_psq [t * F_OUT + f];
    }
    ss[g][f] = s; sq[g][f] = q;
    __syncthreads();
    if (g == 0) {
        s = ss[0][f] + ss[1][f] + ss[2][f] + ss[3][f];
        q = sq[0][f] + sq[1][f] + sq[2][f] + sq[3][f];
        const float inv = 1.0f / (float)M_TOTAL;
        float mean = s * inv;
        float var  = q * inv - mean * mean;
        float sc   = gamma[f] * rsqrtf(var + 1e-3f);
        g_scale[f] = sc;
        g_shift[f] = beta[f] - mean * sc;
    }
}

// K3: normalize + relu (vectorized float4)
__global__ __launch_bounds__(512) void norm_kernel(float* __restrict__ out) {
    const int idx = blockIdx.x * 512 + threadIdx.x;    // float4 index
    float4 y = *(const float4*)&g_y[(size_t)idx * 4];
    const int fb = (idx & 63) * 4;                     // F_OUT/4 = 64 groups
    float4 sc = *(const float4*)&g_scale[fb];
    float4 sh = *(const float4*)&g_shift[fb];
    float4 o;
    o.x = fmaxf(fmaf(y.x, sc.x, sh.x), 0.f);
    o.y = fmaxf(fmaf(y.y, sc.y, sh.y), 0.f);
    o.z = fmaxf(fmaf(y.z, sc.z, sh.z), 0.f);
    o.w = fmaxf(fmaf(y.w, sc.w, sh.w), 0.f);
    *(float4*)&out[(size_t)idx * 4] = o;
}

extern "C" void kernel_launch(void* const* d_in, const int* in_sizes, int n_in,
                              void* d_out, int out_size) {
    const float* x     = (const float*)d_in[0];
    const float* W     = (const float*)d_in[1];
    // d_in[2] = conv bias b: cancels exactly under BatchNorm -> unused
    const float* gamma = (const float*)d_in[3];
    const float* beta  = (const float*)d_in[4];

    cudaFuncSetAttribute(gemm_kernel, cudaFuncAttributeMaxDynamicSharedMemorySize, SM_TOT);

    wsplit_kernel<<<32, 256>>>(W);
    gemm_kernel<<<dim3(2, MT), 256, SM_TOT>>>(x);
    stats_kernel<<<1, 1024>>>(gamma, beta);
    norm_kernel<<<(M_TOTAL * F_OUT) / (512 * 4), 512>>>((float*)d_out);
}